// round 2
// baseline (speedup 1.0000x reference)
#include <cuda_runtime.h>
#include <math.h>

#define NN 100000
#define HH 64

// Scratch (static __device__ arrays; no allocation in kernel_launch)
__device__ float d_deg [NN];
__device__ float d_dinv[NN];
__device__ float d_g   [(size_t)NN * HH];
__device__ float d_accA[(size_t)NN * HH];
__device__ float d_accB[(size_t)NN * HH];

// ---------------------------------------------------------------------------
// degree / dinv
// ---------------------------------------------------------------------------
__global__ void init_deg_kernel(int n) {
    int i = blockIdx.x * blockDim.x + threadIdx.x;
    if (i < n) d_deg[i] = 1.0f;          // self loop
}

__global__ void count_deg_kernel(const int* __restrict__ col, int E) {
    int e = blockIdx.x * blockDim.x + threadIdx.x;
    if (e < E) atomicAdd(&d_deg[col[e]], 1.0f);
}

__global__ void dinv_kernel(int n) {
    int i = blockIdx.x * blockDim.x + threadIdx.x;
    if (i < n) d_dinv[i] = rsqrtf(d_deg[i]);
}

// ---------------------------------------------------------------------------
// GEMM: g[r,:] = prep(src[r,:]) @ W * dinv[r]    also acc = g (self-loop init)
// prep (layers 2,3): v = elu(v * dinv[r] + b_prev)    (previous layer epilogue)
// Tile: 64 rows x 64 cols per block, 256 threads, 4 threads/row x 16 cols.
// ---------------------------------------------------------------------------
__global__ void __launch_bounds__(256) gemm_kernel(
    const float* __restrict__ src, const float* __restrict__ W,
    const float* __restrict__ b_prev, int prep,
    float* __restrict__ g, float* __restrict__ acc, int n)
{
    __shared__ float xs[64][65];   // padded: avoid bank conflicts on xs[rl][k]
    __shared__ float Ws[64][64];   // Ws[k][c]

    int t = threadIdx.x;
    int row0 = blockIdx.x << 6;

    for (int i = t; i < 4096; i += 256)
        Ws[i >> 6][i & 63] = W[i];

    for (int i = t; i < 4096; i += 256) {
        int r = i >> 6, c = i & 63;
        int gr = row0 + r;
        float v = 0.0f;
        if (gr < n) {
            v = src[(size_t)gr * 64 + c];
            if (prep) {
                v = v * d_dinv[gr] + b_prev[c];
                v = (v > 0.0f) ? v : expm1f(v);
            }
        }
        xs[r][c] = v;
    }
    __syncthreads();

    int rl = t >> 2;
    int cp = (t & 3) << 4;
    int gr = row0 + rl;

    float a[16];
#pragma unroll
    for (int j = 0; j < 16; j++) a[j] = 0.0f;

#pragma unroll
    for (int k = 0; k < 64; k++) {
        float xv = xs[rl][k];
        const float4* wp = (const float4*)&Ws[k][cp];
        float4 w0 = wp[0], w1 = wp[1], w2 = wp[2], w3 = wp[3];
        a[0]  += xv * w0.x;  a[1]  += xv * w0.y;  a[2]  += xv * w0.z;  a[3]  += xv * w0.w;
        a[4]  += xv * w1.x;  a[5]  += xv * w1.y;  a[6]  += xv * w1.z;  a[7]  += xv * w1.w;
        a[8]  += xv * w2.x;  a[9]  += xv * w2.y;  a[10] += xv * w2.z;  a[11] += xv * w2.w;
        a[12] += xv * w3.x;  a[13] += xv * w3.y;  a[14] += xv * w3.z;  a[15] += xv * w3.w;
    }

    if (gr < n) {
        float s = d_dinv[gr];
        float4* gp = (float4*)&g[(size_t)gr * 64 + cp];
        float4* ap = (float4*)&acc[(size_t)gr * 64 + cp];
#pragma unroll
        for (int q = 0; q < 4; q++) {
            float4 v;
            v.x = a[4*q+0] * s; v.y = a[4*q+1] * s;
            v.z = a[4*q+2] * s; v.w = a[4*q+3] * s;
            gp[q] = v;
            ap[q] = v;
        }
    }
}

// ---------------------------------------------------------------------------
// Edge scatter: acc[col[e],:] += g[row[e],:]
// 16 threads per edge, one float4 each; vectorized L2 reduction (sm_90+).
// ---------------------------------------------------------------------------
__global__ void __launch_bounds__(256) scatter_kernel(
    const int* __restrict__ row, const int* __restrict__ col,
    const float* __restrict__ g, float* __restrict__ acc, int E)
{
    long long tid = (long long)blockIdx.x * blockDim.x + threadIdx.x;
    int e = (int)(tid >> 4);
    if (e >= E) return;
    int j = (int)(tid & 15);

    int r = row[e];
    int c = col[e];

    float4 v = ((const float4*)g)[(size_t)r * 16 + j];
    float4* dst = (float4*)acc + (size_t)c * 16 + j;
    asm volatile("red.global.add.v4.f32 [%0], {%1,%2,%3,%4};"
                 :: "l"(dst), "f"(v.x), "f"(v.y), "f"(v.z), "f"(v.w)
                 : "memory");
}

// ---------------------------------------------------------------------------
// Final epilogue (layer 3): out = acc * dinv + b3   (no ELU)
// ---------------------------------------------------------------------------
__global__ void __launch_bounds__(256) finalize_kernel(
    const float* __restrict__ acc, const float* __restrict__ b,
    float* __restrict__ out, int n)
{
    int idx = blockIdx.x * blockDim.x + threadIdx.x;  // over n*16 float4s
    if (idx >= n * 16) return;
    int i = idx >> 4;
    int j = idx & 15;
    float4 v  = ((const float4*)acc)[idx];
    float4 bb = ((const float4*)b)[j];
    float s = d_dinv[i];
    v.x = v.x * s + bb.x;
    v.y = v.y * s + bb.y;
    v.z = v.z * s + bb.z;
    v.w = v.w * s + bb.w;
    ((float4*)out)[idx] = v;
}

// ---------------------------------------------------------------------------
extern "C" void kernel_launch(void* const* d_in, const int* in_sizes, int n_in,
                              void* d_out, int out_size)
{
    const float* x  = (const float*)d_in[0];
    const int*   ei = (const int*)  d_in[1];
    const float* W1 = (const float*)d_in[2];
    const float* b1 = (const float*)d_in[3];
    const float* W2 = (const float*)d_in[4];
    const float* b2 = (const float*)d_in[5];
    const float* W3 = (const float*)d_in[6];
    const float* b3 = (const float*)d_in[7];

    int n = in_sizes[0] / HH;        // 100000
    int E = in_sizes[1] / 2;         // 1600000
    const int* row = ei;             // sources
    const int* col = ei + E;         // targets

    float *g, *accA, *accB;
    cudaGetSymbolAddress((void**)&g,    d_g);
    cudaGetSymbolAddress((void**)&accA, d_accA);
    cudaGetSymbolAddress((void**)&accB, d_accB);

    int nb256 = (n + 255) / 256;
    init_deg_kernel<<<nb256, 256>>>(n);
    count_deg_kernel<<<(E + 255) / 256, 256>>>(col, E);
    dinv_kernel<<<nb256, 256>>>(n);

    int gblocks = (n + 63) / 64;
    long long st = (long long)E * 16;
    int sblocks = (int)((st + 255) / 256);
    int fblocks = (n * 16 + 255) / 256;

    // Layer 1: x -> accA
    gemm_kernel<<<gblocks, 256>>>(x, W1, nullptr, 0, g, accA, n);
    scatter_kernel<<<sblocks, 256>>>(row, col, g, accA, E);

    // Layer 2: elu(accA*dinv+b1) -> accB
    gemm_kernel<<<gblocks, 256>>>(accA, W2, b1, 1, g, accB, n);
    scatter_kernel<<<sblocks, 256>>>(row, col, g, accB, E);

    // Layer 3: elu(accB*dinv+b2) -> accA
    gemm_kernel<<<gblocks, 256>>>(accB, W3, b2, 1, g, accA, n);
    scatter_kernel<<<sblocks, 256>>>(row, col, g, accA, E);

    // out = accA*dinv + b3
    finalize_kernel<<<fblocks, 256>>>(accA, b3, (float*)d_out, n);
}

// round 3
// speedup vs baseline: 2.2340x; 2.2340x over previous
#include <cuda_runtime.h>
#include <math.h>

#define NN 100000
#define HH 64
#define EE 1600000

// ---------------------------------------------------------------------------
// Scratch (__device__ globals; no allocation anywhere)
// ---------------------------------------------------------------------------
__device__ int   d_hist  [NN];
__device__ int   d_rowptr[NN + 1];
__device__ int   d_cursor[NN];
__device__ int   d_part  [NN];
__device__ int   d_bsum  [512];
__device__ int   d_csr   [EE];
__device__ float d_dinv  [NN];
__device__ float d_g     [(size_t)NN * HH];
__device__ float d_bufA  [(size_t)NN * HH];
__device__ float d_bufB  [(size_t)NN * HH];

// ---------------------------------------------------------------------------
// Setup: histogram of targets, dinv, exclusive scan -> rowptr, bucket fill
// ---------------------------------------------------------------------------
__global__ void count_hist_kernel(const int* __restrict__ col, int E) {
    int e = blockIdx.x * blockDim.x + threadIdx.x;
    if (e < E) atomicAdd(&d_hist[col[e]], 1);
}

__global__ void dinv_kernel(int n) {
    int i = blockIdx.x * blockDim.x + threadIdx.x;
    if (i < n) d_dinv[i] = rsqrtf((float)(1 + d_hist[i]));  // +1 self loop
}

__global__ void scan1_kernel(int n) {
    __shared__ int sh[256];
    int t = threadIdx.x;
    int i = blockIdx.x * 256 + t;
    int v = (i < n) ? d_hist[i] : 0;
    sh[t] = v;
    __syncthreads();
    for (int off = 1; off < 256; off <<= 1) {
        int u = (t >= off) ? sh[t - off] : 0;
        __syncthreads();
        if (t >= off) sh[t] += u;
        __syncthreads();
    }
    if (i < n) d_part[i] = sh[t] - v;         // exclusive within block
    if (t == 255) d_bsum[blockIdx.x] = sh[255];
}

__global__ void scan2_kernel(int nb) {
    __shared__ int sh[512];
    int t = threadIdx.x;
    int v = (t < nb) ? d_bsum[t] : 0;
    sh[t] = v;
    __syncthreads();
    for (int off = 1; off < 512; off <<= 1) {
        int u = (t >= off) ? sh[t - off] : 0;
        __syncthreads();
        if (t >= off) sh[t] += u;
        __syncthreads();
    }
    if (t < nb) d_bsum[t] = sh[t] - v;        // exclusive block offsets
}

__global__ void scan3_kernel(int n, int E) {
    int i = blockIdx.x * blockDim.x + threadIdx.x;
    if (i < n) {
        int v = d_part[i] + d_bsum[i >> 8];
        d_rowptr[i] = v;
        d_cursor[i] = v;
    }
    if (i == 0) d_rowptr[n] = E;
}

__global__ void fill_kernel(const int* __restrict__ row,
                            const int* __restrict__ col, int E) {
    int e = blockIdx.x * blockDim.x + threadIdx.x;
    if (e < E) {
        int c = col[e];
        int p = atomicAdd(&d_cursor[c], 1);
        d_csr[p] = row[e];
    }
}

// ---------------------------------------------------------------------------
// GEMM: g[r,:] = prep(src[r,:]) @ W * dinv[r]
// prep (layers 2,3): v = elu(v * dinv[r] + b_prev)
// Tile: 128 rows x 64 cols, 256 threads; per-thread 4 rows x 8 cols,
// packed fma.rn.f32x2 accumulators. 51.2 KB dynamic smem.
// ---------------------------------------------------------------------------
#define XS_STRIDE 68

__global__ void __launch_bounds__(256) gemm_kernel(
    const float* __restrict__ src, const float* __restrict__ W,
    const float* __restrict__ b_prev, int prep,
    float* __restrict__ g, int n)
{
    extern __shared__ float sm[];
    float* xs = sm;                         // [128][68]
    float* Ws = sm + 128 * XS_STRIDE;       // [64][64]

    int t = threadIdx.x;
    int row0 = blockIdx.x << 7;

    for (int i = t; i < 4096; i += 256) Ws[i] = W[i];

    const float4* src4 = (const float4*)src;
#pragma unroll
    for (int j = 0; j < 8; j++) {
        int f  = t + (j << 8);              // float4 index within 128x64 tile
        int r  = f >> 4;
        int c4 = (f & 15) << 2;
        int gr = row0 + r;
        float4 v = make_float4(0.f, 0.f, 0.f, 0.f);
        if (gr < n) {
            v = src4[(size_t)gr * 16 + (c4 >> 2)];
            if (prep) {
                float dv = d_dinv[gr];
                v.x = v.x * dv + b_prev[c4 + 0]; v.x = (v.x > 0.f) ? v.x : expm1f(v.x);
                v.y = v.y * dv + b_prev[c4 + 1]; v.y = (v.y > 0.f) ? v.y : expm1f(v.y);
                v.z = v.z * dv + b_prev[c4 + 2]; v.z = (v.z > 0.f) ? v.z : expm1f(v.z);
                v.w = v.w * dv + b_prev[c4 + 3]; v.w = (v.w > 0.f) ? v.w : expm1f(v.w);
            }
        }
        *(float4*)&xs[r * XS_STRIDE + c4] = v;
    }
    __syncthreads();

    int tx = t & 7;
    int ty = t >> 3;
    int c0 = tx << 3;

    unsigned long long acc[4][4];
#pragma unroll
    for (int i = 0; i < 4; i++)
#pragma unroll
        for (int j = 0; j < 4; j++) acc[i][j] = 0ull;

#pragma unroll 8
    for (int k = 0; k < 64; k++) {
        float4 w0 = *(const float4*)&Ws[(k << 6) + c0];
        float4 w1 = *(const float4*)&Ws[(k << 6) + c0 + 4];
        unsigned long long wp0, wp1, wp2, wp3;
        asm("mov.b64 %0, {%1,%2};" : "=l"(wp0) : "f"(w0.x), "f"(w0.y));
        asm("mov.b64 %0, {%1,%2};" : "=l"(wp1) : "f"(w0.z), "f"(w0.w));
        asm("mov.b64 %0, {%1,%2};" : "=l"(wp2) : "f"(w1.x), "f"(w1.y));
        asm("mov.b64 %0, {%1,%2};" : "=l"(wp3) : "f"(w1.z), "f"(w1.w));
#pragma unroll
        for (int i = 0; i < 4; i++) {
            float xv = xs[(ty + (i << 5)) * XS_STRIDE + k];
            unsigned long long xp;
            asm("mov.b64 %0, {%1,%1};" : "=l"(xp) : "f"(xv));
            asm("fma.rn.f32x2 %0, %1, %2, %0;" : "+l"(acc[i][0]) : "l"(xp), "l"(wp0));
            asm("fma.rn.f32x2 %0, %1, %2, %0;" : "+l"(acc[i][1]) : "l"(xp), "l"(wp1));
            asm("fma.rn.f32x2 %0, %1, %2, %0;" : "+l"(acc[i][2]) : "l"(xp), "l"(wp2));
            asm("fma.rn.f32x2 %0, %1, %2, %0;" : "+l"(acc[i][3]) : "l"(xp), "l"(wp3));
        }
    }

#pragma unroll
    for (int i = 0; i < 4; i++) {
        int gr = row0 + ty + (i << 5);
        if (gr < n) {
            float dv = d_dinv[gr];
            float a[8];
#pragma unroll
            for (int j = 0; j < 4; j++) {
                float lo, hi;
                asm("mov.b64 {%0,%1}, %2;" : "=f"(lo), "=f"(hi) : "l"(acc[i][j]));
                a[2 * j]     = lo * dv;
                a[2 * j + 1] = hi * dv;
            }
            float4* gp = (float4*)&g[(size_t)gr * 64 + c0];
            gp[0] = make_float4(a[0], a[1], a[2], a[3]);
            gp[1] = make_float4(a[4], a[5], a[6], a[7]);
        }
    }
}

// ---------------------------------------------------------------------------
// Aggregation: out[c,:] = g[c,:] + sum_{r in CSR[c]} g[r,:]
// One warp per node, float2 per lane. Optional final epilogue (*dinv + b).
// ---------------------------------------------------------------------------
__global__ void __launch_bounds__(256) agg_kernel(
    const float* __restrict__ g, float* __restrict__ out,
    int n, int final_flag, const float* __restrict__ b)
{
    int w    = (blockIdx.x * 256 + threadIdx.x) >> 5;
    int lane = threadIdx.x & 31;
    if (w >= n) return;

    const float2* g2 = (const float2*)g;
    float2 acc = g2[(size_t)w * 32 + lane];          // self loop

    int s = d_rowptr[w];
    int e = d_rowptr[w + 1];
    int i = s;
    for (; i + 4 <= e; i += 4) {
        int r0 = d_csr[i], r1 = d_csr[i + 1], r2 = d_csr[i + 2], r3 = d_csr[i + 3];
        float2 v0 = g2[(size_t)r0 * 32 + lane];
        float2 v1 = g2[(size_t)r1 * 32 + lane];
        float2 v2 = g2[(size_t)r2 * 32 + lane];
        float2 v3 = g2[(size_t)r3 * 32 + lane];
        acc.x += v0.x; acc.y += v0.y;
        acc.x += v1.x; acc.y += v1.y;
        acc.x += v2.x; acc.y += v2.y;
        acc.x += v3.x; acc.y += v3.y;
    }
    for (; i < e; i++) {
        int r = d_csr[i];
        float2 v = g2[(size_t)r * 32 + lane];
        acc.x += v.x; acc.y += v.y;
    }

    if (final_flag) {
        float dv = d_dinv[w];
        float2 bb = ((const float2*)b)[lane];
        acc.x = acc.x * dv + bb.x;
        acc.y = acc.y * dv + bb.y;
    }
    ((float2*)out)[(size_t)w * 32 + lane] = acc;
}

// ---------------------------------------------------------------------------
extern "C" void kernel_launch(void* const* d_in, const int* in_sizes, int n_in,
                              void* d_out, int out_size)
{
    const float* x  = (const float*)d_in[0];
    const int*   ei = (const int*)  d_in[1];
    const float* W1 = (const float*)d_in[2];
    const float* b1 = (const float*)d_in[3];
    const float* W2 = (const float*)d_in[4];
    const float* b2 = (const float*)d_in[5];
    const float* W3 = (const float*)d_in[6];
    const float* b3 = (const float*)d_in[7];

    int n = in_sizes[0] / HH;   // 100000
    int E = in_sizes[1] / 2;    // 1600000
    const int* row = ei;        // sources
    const int* col = ei + E;    // targets

    void *hist_p, *g_p, *A_p, *B_p;
    cudaGetSymbolAddress(&hist_p, d_hist);
    cudaGetSymbolAddress(&g_p, d_g);
    cudaGetSymbolAddress(&A_p, d_bufA);
    cudaGetSymbolAddress(&B_p, d_bufB);
    float* g = (float*)g_p;
    float* A = (float*)A_p;
    float* B = (float*)B_p;

    static int smem_set = 0;
    int gemm_smem = (128 * XS_STRIDE + 4096) * sizeof(float);  // 51200 B
    if (!smem_set) {
        cudaFuncSetAttribute(gemm_kernel,
                             cudaFuncAttributeMaxDynamicSharedMemorySize, gemm_smem);
        smem_set = 1;
    }

    int nbN = (n + 255) / 256;
    int nbE = (E + 255) / 256;
    int nscan = (n + 255) / 256;                 // 391 blocks

    // ---- CSR build ----
    cudaMemsetAsync(hist_p, 0, (size_t)n * sizeof(int));
    count_hist_kernel<<<nbE, 256>>>(col, E);
    dinv_kernel<<<nbN, 256>>>(n);
    scan1_kernel<<<nscan, 256>>>(n);
    scan2_kernel<<<1, 512>>>(nscan);
    scan3_kernel<<<nbN, 256>>>(n, E);
    fill_kernel<<<nbE, 256>>>(row, col, E);

    int gblocks = (n + 127) / 128;
    int ablocks = (n * 32 + 255) / 256;          // one warp per node

    // Layer 1
    gemm_kernel<<<gblocks, 256, gemm_smem>>>(x, W1, nullptr, 0, g, n);
    agg_kernel<<<ablocks, 256>>>(g, A, n, 0, nullptr);
    // Layer 2
    gemm_kernel<<<gblocks, 256, gemm_smem>>>(A, W2, b1, 1, g, n);
    agg_kernel<<<ablocks, 256>>>(g, B, n, 0, nullptr);
    // Layer 3
    gemm_kernel<<<gblocks, 256, gemm_smem>>>(B, W3, b2, 1, g, n);
    agg_kernel<<<ablocks, 256>>>(g, (float*)d_out, n, 1, b3);
}

// round 4
// speedup vs baseline: 2.5226x; 1.1292x over previous
#include <cuda_runtime.h>
#include <cuda_fp16.h>
#include <math.h>

#define NN 100000
#define HH 64
#define EE 1600000

// ---------------------------------------------------------------------------
// Scratch (__device__ globals; no allocation anywhere)
// ---------------------------------------------------------------------------
__device__ int     d_hist  [NN];
__device__ int     d_rowptr[NN + 1];
__device__ int     d_cursor[NN];
__device__ int     d_part  [NN];
__device__ int     d_bsum  [512];
__device__ int     d_csr   [EE];
__device__ float   d_dinv  [NN];
__device__ __half2 d_g     [(size_t)NN * (HH / 2)];   // g in fp16 (gather payload)
__device__ float   d_bufA  [(size_t)NN * HH];
__device__ float   d_bufB  [(size_t)NN * HH];

// ---------------------------------------------------------------------------
// Setup: histogram of targets -> scan -> rowptr/cursor/dinv -> bucket fill
// ---------------------------------------------------------------------------
__global__ void count_hist_kernel(const int* __restrict__ col, int E) {
    int e = blockIdx.x * blockDim.x + threadIdx.x;
    if (e < E) atomicAdd(&d_hist[col[e]], 1);
}

__global__ void scan1_kernel(int n) {
    __shared__ int sh[256];
    int t = threadIdx.x;
    int i = blockIdx.x * 256 + t;
    int v = (i < n) ? d_hist[i] : 0;
    sh[t] = v;
    __syncthreads();
    for (int off = 1; off < 256; off <<= 1) {
        int u = (t >= off) ? sh[t - off] : 0;
        __syncthreads();
        if (t >= off) sh[t] += u;
        __syncthreads();
    }
    if (i < n) d_part[i] = sh[t] - v;          // exclusive within block
    if (t == 255) d_bsum[blockIdx.x] = sh[255];
}

__global__ void scan2_kernel(int nb) {
    __shared__ int sh[512];
    int t = threadIdx.x;
    int v = (t < nb) ? d_bsum[t] : 0;
    sh[t] = v;
    __syncthreads();
    for (int off = 1; off < 512; off <<= 1) {
        int u = (t >= off) ? sh[t - off] : 0;
        __syncthreads();
        if (t >= off) sh[t] += u;
        __syncthreads();
    }
    if (t < nb) d_bsum[t] = sh[t] - v;         // exclusive block offsets
}

// rowptr + cursor + dinv in one pass
__global__ void scan3_kernel(int n, int E) {
    int i = blockIdx.x * blockDim.x + threadIdx.x;
    if (i < n) {
        int v = d_part[i] + d_bsum[i >> 8];
        d_rowptr[i] = v;
        d_cursor[i] = v;
        d_dinv[i]   = rsqrtf((float)(1 + d_hist[i]));   // +1 self loop
    }
    if (i == 0) d_rowptr[n] = E;
}

__global__ void fill_kernel(const int* __restrict__ row,
                            const int* __restrict__ col, int E) {
    int e = blockIdx.x * blockDim.x + threadIdx.x;
    if (e < E) {
        int c = col[e];
        int p = atomicAdd(&d_cursor[c], 1);
        d_csr[p] = row[e];
    }
}

// ---------------------------------------------------------------------------
// GEMM: g[r,:] = fp16( prep(src[r,:]) @ W * dinv[r] )
// prep (layers 2,3): v = elu(v * dinv[r] + b_prev)   (previous layer epilogue)
// Tile: 128 rows x 64 cols, 128 threads; per-thread 8 rows x 8 cols,
// packed fma.rn.f32x2 accumulators. 51.2 KB dynamic smem.
// ---------------------------------------------------------------------------
#define XS_STRIDE 68

__global__ void __launch_bounds__(128) gemm_kernel(
    const float* __restrict__ src, const float* __restrict__ W,
    const float* __restrict__ b_prev, int prep,
    __half2* __restrict__ g, int n)
{
    extern __shared__ float sm[];
    float* xs = sm;                         // [128][68]
    float* Ws = sm + 128 * XS_STRIDE;       // [64][64]

    int t = threadIdx.x;
    int row0 = blockIdx.x << 7;

    for (int i = t; i < 4096; i += 128) Ws[i] = W[i];

    const float4* src4 = (const float4*)src;
#pragma unroll
    for (int j = 0; j < 16; j++) {
        int f  = t + (j << 7);              // float4 index within 128x64 tile
        int r  = f >> 4;
        int c4 = (f & 15) << 2;
        int gr = row0 + r;
        float4 v = make_float4(0.f, 0.f, 0.f, 0.f);
        if (gr < n) {
            v = src4[(size_t)gr * 16 + (c4 >> 2)];
            if (prep) {
                float dv = d_dinv[gr];
                v.x = v.x * dv + b_prev[c4 + 0]; v.x = (v.x > 0.f) ? v.x : expm1f(v.x);
                v.y = v.y * dv + b_prev[c4 + 1]; v.y = (v.y > 0.f) ? v.y : expm1f(v.y);
                v.z = v.z * dv + b_prev[c4 + 2]; v.z = (v.z > 0.f) ? v.z : expm1f(v.z);
                v.w = v.w * dv + b_prev[c4 + 3]; v.w = (v.w > 0.f) ? v.w : expm1f(v.w);
            }
        }
        *(float4*)&xs[r * XS_STRIDE + c4] = v;
    }
    __syncthreads();

    int tx = t & 7;          // col octet -> c0
    int ty = t >> 3;         // 0..15; rows ty + 16*i
    int c0 = tx << 3;

    unsigned long long acc[8][4];
#pragma unroll
    for (int i = 0; i < 8; i++)
#pragma unroll
        for (int j = 0; j < 4; j++) acc[i][j] = 0ull;

#pragma unroll 4
    for (int k = 0; k < 64; k++) {
        float4 w0 = *(const float4*)&Ws[(k << 6) + c0];
        float4 w1 = *(const float4*)&Ws[(k << 6) + c0 + 4];
        unsigned long long wp0, wp1, wp2, wp3;
        asm("mov.b64 %0, {%1,%2};" : "=l"(wp0) : "f"(w0.x), "f"(w0.y));
        asm("mov.b64 %0, {%1,%2};" : "=l"(wp1) : "f"(w0.z), "f"(w0.w));
        asm("mov.b64 %0, {%1,%2};" : "=l"(wp2) : "f"(w1.x), "f"(w1.y));
        asm("mov.b64 %0, {%1,%2};" : "=l"(wp3) : "f"(w1.z), "f"(w1.w));
#pragma unroll
        for (int i = 0; i < 8; i++) {
            float xv = xs[(ty + (i << 4)) * XS_STRIDE + k];
            unsigned long long xp;
            asm("mov.b64 %0, {%1,%1};" : "=l"(xp) : "f"(xv));
            asm("fma.rn.f32x2 %0, %1, %2, %0;" : "+l"(acc[i][0]) : "l"(xp), "l"(wp0));
            asm("fma.rn.f32x2 %0, %1, %2, %0;" : "+l"(acc[i][1]) : "l"(xp), "l"(wp1));
            asm("fma.rn.f32x2 %0, %1, %2, %0;" : "+l"(acc[i][2]) : "l"(xp), "l"(wp2));
            asm("fma.rn.f32x2 %0, %1, %2, %0;" : "+l"(acc[i][3]) : "l"(xp), "l"(wp3));
        }
    }

#pragma unroll
    for (int i = 0; i < 8; i++) {
        int gr = row0 + ty + (i << 4);
        if (gr < n) {
            float dv = d_dinv[gr];
            __half2 h[4];
#pragma unroll
            for (int j = 0; j < 4; j++) {
                float lo, hi;
                asm("mov.b64 {%0,%1}, %2;" : "=f"(lo), "=f"(hi) : "l"(acc[i][j]));
                h[j] = __floats2half2_rn(lo * dv, hi * dv);
            }
            // 8 halves = 16 B, aligned (tx*16 B within 128 B row)
            float4* grow = (float4*)(g + (size_t)gr * 32);
            grow[tx] = *(float4*)h;
        }
    }
}

// ---------------------------------------------------------------------------
// Aggregation: out[c,:] = g[c,:] + sum_{r in CSR[c]} g[r,:]   (fp32 accum)
// One warp per node; each neighbor row is exactly one 128 B line (half2/lane).
// Optional final epilogue (*dinv + b).
// ---------------------------------------------------------------------------
__global__ void __launch_bounds__(256) agg_kernel(
    const __half2* __restrict__ g, float* __restrict__ out,
    int n, int final_flag, const float* __restrict__ b)
{
    int w    = (blockIdx.x * 256 + threadIdx.x) >> 5;
    int lane = threadIdx.x & 31;
    if (w >= n) return;

    float2 acc = __half22float2(g[(size_t)w * 32 + lane]);   // self loop

    int s = d_rowptr[w];
    int e = d_rowptr[w + 1];
    int i = s;
    for (; i + 4 <= e; i += 4) {
        int r0 = d_csr[i], r1 = d_csr[i + 1], r2 = d_csr[i + 2], r3 = d_csr[i + 3];
        float2 v0 = __half22float2(g[(size_t)r0 * 32 + lane]);
        float2 v1 = __half22float2(g[(size_t)r1 * 32 + lane]);
        float2 v2 = __half22float2(g[(size_t)r2 * 32 + lane]);
        float2 v3 = __half22float2(g[(size_t)r3 * 32 + lane]);
        acc.x += v0.x; acc.y += v0.y;
        acc.x += v1.x; acc.y += v1.y;
        acc.x += v2.x; acc.y += v2.y;
        acc.x += v3.x; acc.y += v3.y;
    }
    for (; i < e; i++) {
        float2 v = __half22float2(g[(size_t)d_csr[i] * 32 + lane]);
        acc.x += v.x; acc.y += v.y;
    }

    if (final_flag) {
        float dv = d_dinv[w];
        float2 bb = ((const float2*)b)[lane];
        acc.x = acc.x * dv + bb.x;
        acc.y = acc.y * dv + bb.y;
    }
    ((float2*)out)[(size_t)w * 32 + lane] = acc;
}

// ---------------------------------------------------------------------------
extern "C" void kernel_launch(void* const* d_in, const int* in_sizes, int n_in,
                              void* d_out, int out_size)
{
    const float* x  = (const float*)d_in[0];
    const int*   ei = (const int*)  d_in[1];
    const float* W1 = (const float*)d_in[2];
    const float* b1 = (const float*)d_in[3];
    const float* W2 = (const float*)d_in[4];
    const float* b2 = (const float*)d_in[5];
    const float* W3 = (const float*)d_in[6];
    const float* b3 = (const float*)d_in[7];

    int n = in_sizes[0] / HH;   // 100000
    int E = in_sizes[1] / 2;    // 1600000
    const int* row = ei;        // sources
    const int* col = ei + E;    // targets

    void *hist_p, *g_p, *A_p, *B_p;
    cudaGetSymbolAddress(&hist_p, d_hist);
    cudaGetSymbolAddress(&g_p, d_g);
    cudaGetSymbolAddress(&A_p, d_bufA);
    cudaGetSymbolAddress(&B_p, d_bufB);
    __half2* g = (__half2*)g_p;
    float*   A = (float*)A_p;
    float*   B = (float*)B_p;

    int gemm_smem = (128 * XS_STRIDE + 4096) * sizeof(float);  // 51200 B
    cudaFuncSetAttribute(gemm_kernel,
                         cudaFuncAttributeMaxDynamicSharedMemorySize, gemm_smem);

    int nbN = (n + 255) / 256;
    int nbE = (E + 255) / 256;
    int nscan = (n + 255) / 256;                 // 391 blocks

    // ---- CSR build ----
    cudaMemsetAsync(hist_p, 0, (size_t)n * sizeof(int));
    count_hist_kernel<<<nbE, 256>>>(col, E);
    scan1_kernel<<<nscan, 256>>>(n);
    scan2_kernel<<<1, 512>>>(nscan);
    scan3_kernel<<<nbN, 256>>>(n, E);
    fill_kernel<<<nbE, 256>>>(row, col, E);

    int gblocks = (n + 127) / 128;
    int ablocks = (n * 32 + 255) / 256;          // one warp per node

    // Layer 1
    gemm_kernel<<<gblocks, 128, gemm_smem>>>(x, W1, nullptr, 0, g, n);
    agg_kernel<<<ablocks, 256>>>(g, A, n, 0, nullptr);
    // Layer 2
    gemm_kernel<<<gblocks, 128, gemm_smem>>>(A, W2, b1, 1, g, n);
    agg_kernel<<<ablocks, 256>>>(g, B, n, 0, nullptr);
    // Layer 3
    gemm_kernel<<<gblocks, 128, gemm_smem>>>(B, W3, b2, 1, g, n);
    agg_kernel<<<ablocks, 256>>>(g, (float*)d_out, n, 1, b3);
}